// round 8
// baseline (speedup 1.0000x reference)
#include <cuda_runtime.h>
#include <cstdint>

// LinearInterpolator on GB300 — 2-CTA/SM version.
//  smem per CTA: s_x[16384] f32 (64KB) + u16 upper-bound LUT (32KB) = 96.3KB
//  -> 2 CTAs x 1024 threads co-resident = 64 warps/SM (vs 32 before).
//  (y_i, slope_i) lives in a __device__ global float2 table (128KB, L2-hot),
//  gathered with LDG.64 as the final chain link. Prep kernels build LUT + ys.
//  Hot path per sample: cell -> LDS.16 lut -> LDS.32 x[idx] -> rare down-scan
//  -> LDG.64 ys -> FMA. Short chain, high occupancy.

#define LUT_SIZE 16384
#define THREADS  1024

__device__ unsigned short g_lut[LUT_SIZE + 2];
__device__ float2 g_ys[LUT_SIZE + 2];     // (y_i, slope_i); sized for n <= 16386

__device__ __forceinline__ int cell_of(float v, float inv_w, float c0) {
    // Identical instruction sequence in build + main kernels (monotone in v).
    return (int)fmaf(v, inv_w, c0);
}

// lut[j] = clamp(max{i : cell(x_i) <= j}, 0, n-2)  (upper bound for samples in cell j)
__global__ void build_lut_kernel(const float* __restrict__ xp, int n) {
    int j = blockIdx.x * blockDim.x + threadIdx.x;
    if (j > LUT_SIZE + 1) return;
    float x_lo = __ldg(&xp[0]);
    float x_hi = __ldg(&xp[n - 1]);
    float inv_w = __fdiv_rn((float)LUT_SIZE, __fsub_rn(x_hi, x_lo));
    float c0 = __fmul_rn(-x_lo, inv_w);
    int lo = 0, hi = n;
    #pragma unroll 1
    while (lo < hi) {
        int mid = (lo + hi) >> 1;
        if (cell_of(__ldg(&xp[mid]), inv_w, c0) <= j) lo = mid + 1;
        else hi = mid;
    }
    int ub = lo - 1;                 // last knot with cell <= j (>=0 since cell(x0)=0)
    if (ub < 0) ub = 0;
    if (ub > n - 2) ub = n - 2;
    g_lut[j] = (unsigned short)ub;
}

__global__ void build_ys_kernel(const float* __restrict__ xp,
                                const float* __restrict__ yp, int n) {
    int i = blockIdx.x * blockDim.x + threadIdx.x;
    if (i >= n) return;
    float yi = __ldg(&yp[i]);
    float sl = 0.0f;
    if (i < n - 1)
        sl = __fdiv_rn(__ldg(&yp[i + 1]) - yi, __ldg(&xp[i + 1]) - __ldg(&xp[i]));
    g_ys[i] = make_float2(yi, sl);
}

extern __shared__ unsigned char smem_raw[];

__device__ __forceinline__ float interp1(float x,
                                         const float* __restrict__ s_x,
                                         const unsigned short* __restrict__ s_lut,
                                         float inv_w, float c0) {
    int j = cell_of(x, inv_w, c0);
    j = min(j, LUT_SIZE + 1);
    int idx = (int)s_lut[j];
    float xi = s_x[idx];
    // Down-only correction (upper-bound LUT); expected <1 iteration.
    while (xi > x) { xi = s_x[--idx]; }
    float2 ys = __ldg(&g_ys[idx]);        // (y_i, slope_i) from L2-hot table
    return fmaf(ys.y, __fsub_rn(x, xi), ys.x);
}

__global__ __launch_bounds__(THREADS, 2)
void interp_kernel(const float* __restrict__ xs, const float* __restrict__ xp,
                   float* __restrict__ out, int total, int n) {
    float* s_x = reinterpret_cast<float*>(smem_raw);                  // n f32
    unsigned short* s_lut =
        reinterpret_cast<unsigned short*>(smem_raw + (size_t)n * 4);

    for (int i = threadIdx.x; i < n; i += blockDim.x)
        s_x[i] = __ldg(&xp[i]);
    for (int i = threadIdx.x; i < LUT_SIZE + 2; i += blockDim.x)
        s_lut[i] = g_lut[i];
    __syncthreads();

    float x_lo = s_x[0];
    float x_hi = s_x[n - 1];
    float inv_w = __fdiv_rn((float)LUT_SIZE, __fsub_rn(x_hi, x_lo));
    float c0 = __fmul_rn(-x_lo, inv_w);

    int tid = blockIdx.x * blockDim.x + threadIdx.x;
    int stride = gridDim.x * blockDim.x;
    int T4 = total >> 2;

    const float4* __restrict__ xs4 = reinterpret_cast<const float4*>(xs);
    float4* __restrict__ out4 = reinterpret_cast<float4*>(out);

    // ILP = 8: two float4 per iteration.
    for (int t = tid; t < T4; t += 2 * stride) {
        int t2 = t + stride;
        bool hb = t2 < T4;
        float4 a = xs4[t];
        float4 b = hb ? xs4[t2] : a;

        float v[8] = {a.x, a.y, a.z, a.w, b.x, b.y, b.z, b.w};
        float r[8];
        #pragma unroll
        for (int k = 0; k < 8; k++)
            r[k] = interp1(v[k], s_x, s_lut, inv_w, c0);

        out4[t] = make_float4(r[0], r[1], r[2], r[3]);
        if (hb) out4[t2] = make_float4(r[4], r[5], r[6], r[7]);
    }
    for (int t = (T4 << 2) + tid; t < total; t += stride)
        out[t] = interp1(xs[t], s_x, s_lut, inv_w, c0);
}

extern "C" void kernel_launch(void* const* d_in, const int* in_sizes, int n_in,
                              void* d_out, int out_size) {
    const float* xs = (const float*)d_in[0];
    const float* xp = (const float*)d_in[1];
    const float* yp = (const float*)d_in[2];
    float* out = (float*)d_out;
    int total = in_sizes[0];
    int n = in_sizes[1];

    build_lut_kernel<<<(LUT_SIZE + 2 + 255) / 256, 256>>>(xp, n);
    build_ys_kernel<<<(n + 255) / 256, 256>>>(xp, yp, n);

    size_t smem_bytes = (size_t)n * 4 + (size_t)(LUT_SIZE + 2) * 2;
    cudaFuncSetAttribute(interp_kernel,
                         cudaFuncAttributeMaxDynamicSharedMemorySize,
                         (int)smem_bytes);

    int sm_count = 148, dev = 0;
    cudaGetDevice(&dev);
    cudaDeviceGetAttribute(&sm_count, cudaDevAttrMultiProcessorCount, dev);
    if (sm_count <= 0) sm_count = 148;

    interp_kernel<<<2 * sm_count, THREADS, smem_bytes>>>(xs, xp, out, total, n);
}

// round 10
// speedup vs baseline: 2.2451x; 2.2451x over previous
#include <cuda_runtime.h>
#include <cstdint>

// LinearInterpolator on GB300 — speculative-gather version (all-SMEM, 1 CTA/SM).
//  Upper-bound LUT: lut[j] = clamp(max{i : cell(x_i) <= j}, 0, n-2). For a
//  sample x in cell j the true interval index is <= lut[j] (down-only scan).
//  Hot path: LDS.16 lut -> PARALLEL { LDS.32 x[idx], LDS.64 ys[idx] } ->
//  rare down-scan (x only, ys reloaded once at the end) -> FMA.
//  Common-case dependent-LDS chain depth: 2 (was 3 in the 33.2us version).

#define LUT_SIZE 16384
#define THREADS  1024

__device__ unsigned short g_lut[LUT_SIZE + 2];

__device__ __forceinline__ int cell_of(float v, float inv_w, float c0) {
    // Identical instruction sequence in build + main kernels (monotone in v).
    return (int)fmaf(v, inv_w, c0);
}

// lut[j] = last knot index with cell(x_i) <= j, clamped to [0, n-2].
__global__ void build_lut_kernel(const float* __restrict__ xp, int n) {
    int j = blockIdx.x * blockDim.x + threadIdx.x;
    if (j > LUT_SIZE + 1) return;
    float x_lo = __ldg(&xp[0]);
    float x_hi = __ldg(&xp[n - 1]);
    float inv_w = __fdiv_rn((float)LUT_SIZE, __fsub_rn(x_hi, x_lo));
    float c0 = __fmul_rn(-x_lo, inv_w);
    int lo = 0, hi = n;
    #pragma unroll 1
    while (lo < hi) {
        int mid = (lo + hi) >> 1;
        if (cell_of(__ldg(&xp[mid]), inv_w, c0) <= j) lo = mid + 1;
        else hi = mid;
    }
    int ub = lo - 1;                // >= 0 since cell(x_points[0]) = 0 <= j
    if (ub < 0) ub = 0;
    if (ub > n - 2) ub = n - 2;
    g_lut[j] = (unsigned short)ub;
}

extern __shared__ unsigned char smem_raw[];

__device__ __forceinline__ float interp1(float x,
                                         const float* __restrict__ s_x,
                                         const float2* __restrict__ s_ys,
                                         const unsigned short* __restrict__ s_lut,
                                         float inv_w, float c0) {
    int j = cell_of(x, inv_w, c0);
    j = min(j, LUT_SIZE + 1);
    int idx = (int)s_lut[j];
    float xi = s_x[idx];
    float2 ys = s_ys[idx];               // SPECULATIVE: issued parallel with xi
    if (xi > x) {                        // correction needed (~35% of lanes)
        do { xi = s_x[--idx]; } while (xi > x);
        ys = s_ys[idx];                  // single reload after scan settles
    }
    return fmaf(ys.y, __fsub_rn(x, xi), ys.x);
}

__global__ __launch_bounds__(THREADS, 1)
void interp_kernel(const float* __restrict__ xs, const float* __restrict__ xp,
                   const float* __restrict__ yp, float* __restrict__ out,
                   int total, int n) {
    float* s_x = reinterpret_cast<float*>(smem_raw);                    // n f32
    float2* s_ys = reinterpret_cast<float2*>(smem_raw + (size_t)n * 4); // n float2
    unsigned short* s_lut =
        reinterpret_cast<unsigned short*>(smem_raw + (size_t)n * 12);

    // Stage knots (slope precomputed) and LUT into SMEM.
    for (int i = threadIdx.x; i < n; i += blockDim.x) {
        float xi = __ldg(&xp[i]);
        float yi = __ldg(&yp[i]);
        s_x[i] = xi;
        float sl = 0.0f;
        if (i < n - 1)
            sl = __fdiv_rn(__ldg(&yp[i + 1]) - yi, __ldg(&xp[i + 1]) - xi);
        s_ys[i] = make_float2(yi, sl);
    }
    for (int i = threadIdx.x; i < LUT_SIZE + 2; i += blockDim.x)
        s_lut[i] = g_lut[i];
    __syncthreads();

    float x_lo = s_x[0];
    float x_hi = s_x[n - 1];
    float inv_w = __fdiv_rn((float)LUT_SIZE, __fsub_rn(x_hi, x_lo));
    float c0 = __fmul_rn(-x_lo, inv_w);

    int tid = blockIdx.x * blockDim.x + threadIdx.x;
    int stride = gridDim.x * blockDim.x;
    int T4 = total >> 2;

    const float4* __restrict__ xs4 = reinterpret_cast<const float4*>(xs);
    float4* __restrict__ out4 = reinterpret_cast<float4*>(out);

    // ILP = 8: two float4 per iteration; speculative loads let all 16
    // second-level LDS issue before any correction control flow.
    for (int t = tid; t < T4; t += 2 * stride) {
        int t2 = t + stride;
        bool hb = t2 < T4;
        float4 a = xs4[t];
        float4 b = hb ? xs4[t2] : a;

        float v[8] = {a.x, a.y, a.z, a.w, b.x, b.y, b.z, b.w};
        float r[8];
        #pragma unroll
        for (int k = 0; k < 8; k++)
            r[k] = interp1(v[k], s_x, s_ys, s_lut, inv_w, c0);

        out4[t] = make_float4(r[0], r[1], r[2], r[3]);
        if (hb) out4[t2] = make_float4(r[4], r[5], r[6], r[7]);
    }
    for (int t = (T4 << 2) + tid; t < total; t += stride)
        out[t] = interp1(xs[t], s_x, s_ys, s_lut, inv_w, c0);
}

extern "C" void kernel_launch(void* const* d_in, const int* in_sizes, int n_in,
                              void* d_out, int out_size) {
    const float* xs = (const float*)d_in[0];
    const float* xp = (const float*)d_in[1];
    const float* yp = (const float*)d_in[2];
    float* out = (float*)d_out;
    int total = in_sizes[0];
    int n = in_sizes[1];

    build_lut_kernel<<<(LUT_SIZE + 2 + 255) / 256, 256>>>(xp, n);

    size_t smem_bytes = (size_t)n * 12 + (size_t)(LUT_SIZE + 2) * 2;
    cudaFuncSetAttribute(interp_kernel,
                         cudaFuncAttributeMaxDynamicSharedMemorySize,
                         (int)smem_bytes);

    int sm_count = 148, dev = 0;
    cudaGetDevice(&dev);
    cudaDeviceGetAttribute(&sm_count, cudaDevAttrMultiProcessorCount, dev);
    if (sm_count <= 0) sm_count = 148;

    interp_kernel<<<sm_count, THREADS, smem_bytes>>>(xs, xp, yp, out, total, n);
}

// round 11
// speedup vs baseline: 2.4192x; 1.0776x over previous
#include <cuda_runtime.h>
#include <cstdint>

// LinearInterpolator on GB300 — Round-2 layout + batched vector correction.
//  s_x[n] f32 (64KB), s_ys[n] (y_i, slope_i) float2 (128KB), u16 upper-bound
//  LUT (32KB) => 229,380 B smem, 1 CTA x 1024 threads per SM (proven config).
//  interp8: batch 8 lut loads, batch 8 x-probes, then ONE correction loop per
//  8 elements (predicated per-element fixups, reloads overlapped), then batch
//  8 (y,slope) gathers + FMA. One divergence region per 8 elements (was 8).

#define LUT_SIZE 16384
#define THREADS  1024

__device__ unsigned short g_lut[LUT_SIZE + 2];

__device__ __forceinline__ int cell_of(float v, float inv_w, float c0) {
    // Identical instruction sequence in build + main kernels (monotone in v).
    return (int)fmaf(v, inv_w, c0);
}

// lut[j] = last knot index with cell(x_i) <= j, clamped to [0, n-2] (upper bound).
__global__ void build_lut_kernel(const float* __restrict__ xp, int n) {
    int j = blockIdx.x * blockDim.x + threadIdx.x;
    if (j > LUT_SIZE + 1) return;
    float x_lo = __ldg(&xp[0]);
    float x_hi = __ldg(&xp[n - 1]);
    float inv_w = __fdiv_rn((float)LUT_SIZE, __fsub_rn(x_hi, x_lo));
    float c0 = __fmul_rn(-x_lo, inv_w);
    int lo = 0, hi = n;
    #pragma unroll 1
    while (lo < hi) {
        int mid = (lo + hi) >> 1;
        if (cell_of(__ldg(&xp[mid]), inv_w, c0) <= j) lo = mid + 1;
        else hi = mid;
    }
    int ub = lo - 1;                 // >= 0 since cell(x_points[0]) = 0 <= j
    if (ub < 0) ub = 0;
    if (ub > n - 2) ub = n - 2;
    g_lut[j] = (unsigned short)ub;
}

extern __shared__ unsigned char smem_raw[];

__device__ __forceinline__ void interp8(const float v[8], float r[8],
                                        const float* __restrict__ s_x,
                                        const float2* __restrict__ s_ys,
                                        const unsigned short* __restrict__ s_lut,
                                        float inv_w, float c0) {
    int idx[8];
    float xi[8];
    // Level 1: 8 independent LUT loads.
    #pragma unroll
    for (int k = 0; k < 8; k++) {
        int j = cell_of(v[k], inv_w, c0);
        j = min(j, LUT_SIZE + 1);
        idx[k] = (int)s_lut[j];
    }
    // Level 2: 8 independent x-probes.
    #pragma unroll
    for (int k = 0; k < 8; k++)
        xi[k] = s_x[idx[k]];
    // Single batched correction loop: down-scan all 8 chains together.
    bool need = false;
    #pragma unroll
    for (int k = 0; k < 8; k++) need |= (xi[k] > v[k]);
    #pragma unroll 1
    while (need) {
        #pragma unroll
        for (int k = 0; k < 8; k++)
            if (xi[k] > v[k]) xi[k] = s_x[--idx[k]];   // predicated fixup
        need = false;
        #pragma unroll
        for (int k = 0; k < 8; k++) need |= (xi[k] > v[k]);
    }
    // Level 3: 8 independent (y, slope) gathers + FMA epilogue.
    #pragma unroll
    for (int k = 0; k < 8; k++) {
        float2 ys = s_ys[idx[k]];
        r[k] = fmaf(ys.y, __fsub_rn(v[k], xi[k]), ys.x);
    }
}

__device__ __forceinline__ float interp1(float x,
                                         const float* __restrict__ s_x,
                                         const float2* __restrict__ s_ys,
                                         const unsigned short* __restrict__ s_lut,
                                         float inv_w, float c0) {
    int j = cell_of(x, inv_w, c0);
    j = min(j, LUT_SIZE + 1);
    int idx = (int)s_lut[j];
    float xi = s_x[idx];
    while (xi > x) { xi = s_x[--idx]; }
    float2 ys = s_ys[idx];
    return fmaf(ys.y, __fsub_rn(x, xi), ys.x);
}

__global__ __launch_bounds__(THREADS, 1)
void interp_kernel(const float* __restrict__ xs, const float* __restrict__ xp,
                   const float* __restrict__ yp, float* __restrict__ out,
                   int total, int n) {
    float* s_x = reinterpret_cast<float*>(smem_raw);                    // n f32
    float2* s_ys = reinterpret_cast<float2*>(smem_raw + (size_t)n * 4); // n float2
    unsigned short* s_lut =
        reinterpret_cast<unsigned short*>(smem_raw + (size_t)n * 12);

    // Stage knots (slope precomputed) and LUT into SMEM.
    for (int i = threadIdx.x; i < n; i += blockDim.x) {
        float xi = __ldg(&xp[i]);
        float yi = __ldg(&yp[i]);
        s_x[i] = xi;
        float sl = 0.0f;
        if (i < n - 1)
            sl = __fdiv_rn(__ldg(&yp[i + 1]) - yi, __ldg(&xp[i + 1]) - xi);
        s_ys[i] = make_float2(yi, sl);
    }
    for (int i = threadIdx.x; i < LUT_SIZE + 2; i += blockDim.x)
        s_lut[i] = g_lut[i];
    __syncthreads();

    float x_lo = s_x[0];
    float x_hi = s_x[n - 1];
    float inv_w = __fdiv_rn((float)LUT_SIZE, __fsub_rn(x_hi, x_lo));
    float c0 = __fmul_rn(-x_lo, inv_w);

    int tid = blockIdx.x * blockDim.x + threadIdx.x;
    int stride = gridDim.x * blockDim.x;
    int T4 = total >> 2;

    const float4* __restrict__ xs4 = reinterpret_cast<const float4*>(xs);
    float4* __restrict__ out4 = reinterpret_cast<float4*>(out);

    for (int t = tid; t < T4; t += 2 * stride) {
        int t2 = t + stride;
        bool hb = t2 < T4;
        float4 a = xs4[t];
        float4 b = hb ? xs4[t2] : a;

        float v[8] = {a.x, a.y, a.z, a.w, b.x, b.y, b.z, b.w};
        float r[8];
        interp8(v, r, s_x, s_ys, s_lut, inv_w, c0);

        out4[t] = make_float4(r[0], r[1], r[2], r[3]);
        if (hb) out4[t2] = make_float4(r[4], r[5], r[6], r[7]);
    }
    for (int t = (T4 << 2) + tid; t < total; t += stride)
        out[t] = interp1(xs[t], s_x, s_ys, s_lut, inv_w, c0);
}

extern "C" void kernel_launch(void* const* d_in, const int* in_sizes, int n_in,
                              void* d_out, int out_size) {
    const float* xs = (const float*)d_in[0];
    const float* xp = (const float*)d_in[1];
    const float* yp = (const float*)d_in[2];
    float* out = (float*)d_out;
    int total = in_sizes[0];
    int n = in_sizes[1];

    build_lut_kernel<<<(LUT_SIZE + 2 + 255) / 256, 256>>>(xp, n);

    size_t smem_bytes = (size_t)n * 12 + (size_t)(LUT_SIZE + 2) * 2;
    cudaFuncSetAttribute(interp_kernel,
                         cudaFuncAttributeMaxDynamicSharedMemorySize,
                         (int)smem_bytes);

    int sm_count = 148, dev = 0;
    cudaGetDevice(&dev);
    cudaDeviceGetAttribute(&sm_count, cudaDevAttrMultiProcessorCount, dev);
    if (sm_count <= 0) sm_count = 148;

    interp_kernel<<<sm_count, THREADS, smem_bytes>>>(xs, xp, yp, out, total, n);
}

// round 13
// speedup vs baseline: 2.4858x; 1.0275x over previous
#include <cuda_runtime.h>
#include <cstdint>

// LinearInterpolator on GB300 — Round-2 champion + software-pipelined input.
//  s_x[n] f32 (64KB) + s_ys[n] (y,slope) float2 (128KB) + u16 upper-bound LUT
//  (32KB) in SMEM; 1 CTA x 1024 threads per SM (proven best config).
//  Hot path per sample: cell -> LDS.16 lut -> LDS.32 x[idx] -> rare down-scan
//  -> LDS.64 (y,slope) -> FMA.  NEW: next iteration's float4 inputs are
//  prefetched before processing the current ones, so the LDG long-scoreboard
//  wait overlaps the previous batch's smem work instead of preceding it.

#define LUT_SIZE 16384
#define THREADS  1024

__device__ unsigned short g_lut[LUT_SIZE + 2];

__device__ __forceinline__ int cell_of(float v, float inv_w, float c0) {
    // Identical instruction sequence in build + main kernels (monotone in v).
    return (int)fmaf(v, inv_w, c0);
}

// lut[j] = last knot index with cell(x_i) <= j, clamped to [0, n-2] (upper bound).
__global__ void build_lut_kernel(const float* __restrict__ xp, int n) {
    int j = blockIdx.x * blockDim.x + threadIdx.x;
    if (j > LUT_SIZE + 1) return;
    float x_lo = __ldg(&xp[0]);
    float x_hi = __ldg(&xp[n - 1]);
    float inv_w = __fdiv_rn((float)LUT_SIZE, __fsub_rn(x_hi, x_lo));
    float c0 = __fmul_rn(-x_lo, inv_w);
    int lo = 0, hi = n;
    #pragma unroll 1
    while (lo < hi) {
        int mid = (lo + hi) >> 1;
        if (cell_of(__ldg(&xp[mid]), inv_w, c0) <= j) lo = mid + 1;
        else hi = mid;
    }
    int ub = lo - 1;                 // >= 0 since cell(x_points[0]) = 0 <= j
    if (ub < 0) ub = 0;
    if (ub > n - 2) ub = n - 2;
    g_lut[j] = (unsigned short)ub;
}

extern __shared__ unsigned char smem_raw[];

__device__ __forceinline__ float interp1(float x,
                                         const float* __restrict__ s_x,
                                         const float2* __restrict__ s_ys,
                                         const unsigned short* __restrict__ s_lut,
                                         float inv_w, float c0) {
    // x_samp < x_points[n-2] < x_hi  =>  j <= LUT_SIZE-1; table has headroom,
    // so no clamp needed.
    int j = cell_of(x, inv_w, c0);
    int idx = (int)s_lut[j];
    float xi = s_x[idx];
    while (xi > x) { xi = s_x[--idx]; }   // down-only; expected <1 iteration
    float2 ys = s_ys[idx];                // (y_i, slope_i)
    return fmaf(ys.y, __fsub_rn(x, xi), ys.x);
}

__device__ __forceinline__ void do8(const float4& a, const float4& b, bool hb,
                                    int t, int t2, float4* __restrict__ out4,
                                    const float* __restrict__ s_x,
                                    const float2* __restrict__ s_ys,
                                    const unsigned short* __restrict__ s_lut,
                                    float inv_w, float c0) {
    float v[8] = {a.x, a.y, a.z, a.w, b.x, b.y, b.z, b.w};
    float r[8];
    #pragma unroll
    for (int k = 0; k < 8; k++)
        r[k] = interp1(v[k], s_x, s_ys, s_lut, inv_w, c0);
    out4[t] = make_float4(r[0], r[1], r[2], r[3]);
    if (hb) out4[t2] = make_float4(r[4], r[5], r[6], r[7]);
}

__global__ __launch_bounds__(THREADS, 1)
void interp_kernel(const float* __restrict__ xs, const float* __restrict__ xp,
                   const float* __restrict__ yp, float* __restrict__ out,
                   int total, int n) {
    float* s_x = reinterpret_cast<float*>(smem_raw);                    // n f32
    float2* s_ys = reinterpret_cast<float2*>(smem_raw + (size_t)n * 4); // n float2
    unsigned short* s_lut =
        reinterpret_cast<unsigned short*>(smem_raw + (size_t)n * 12);

    // Stage knots (slope precomputed) and LUT into SMEM.
    for (int i = threadIdx.x; i < n; i += blockDim.x) {
        float xi = __ldg(&xp[i]);
        float yi = __ldg(&yp[i]);
        s_x[i] = xi;
        float sl = 0.0f;
        if (i < n - 1)
            sl = __fdiv_rn(__ldg(&yp[i + 1]) - yi, __ldg(&xp[i + 1]) - xi);
        s_ys[i] = make_float2(yi, sl);
    }
    for (int i = threadIdx.x; i < LUT_SIZE + 2; i += blockDim.x)
        s_lut[i] = g_lut[i];
    __syncthreads();

    float x_lo = s_x[0];
    float x_hi = s_x[n - 1];
    float inv_w = __fdiv_rn((float)LUT_SIZE, __fsub_rn(x_hi, x_lo));
    float c0 = __fmul_rn(-x_lo, inv_w);

    int tid = blockIdx.x * blockDim.x + threadIdx.x;
    int stride = gridDim.x * blockDim.x;
    int T4 = total >> 2;

    const float4* __restrict__ xs4 = reinterpret_cast<const float4*>(xs);
    float4* __restrict__ out4 = reinterpret_cast<float4*>(out);

    // Software-pipelined grid-stride loop, ILP = 8 per stage.
    int t = tid;
    bool have = t < T4;
    float4 a = make_float4(0.f, 0.f, 0.f, 0.f), b = a;
    bool hb = false;
    int t2 = t + stride;
    if (have) {
        a = xs4[t];
        hb = t2 < T4;
        b = hb ? xs4[t2] : a;
    }
    #pragma unroll 1
    while (have) {
        int tn = t + 2 * stride;
        bool haven = tn < T4;
        float4 an = a, bn = b;
        bool hbn = false;
        int tn2 = tn + stride;
        if (haven) {                         // PREFETCH next batch's inputs
            an = xs4[tn];
            hbn = tn2 < T4;
            bn = hbn ? xs4[tn2] : an;
        }
        do8(a, b, hb, t, t2, out4, s_x, s_ys, s_lut, inv_w, c0);
        a = an; b = bn; hb = hbn; t = tn; t2 = tn2; have = haven;
    }
    // Scalar tail (total not divisible by 4) — empty for this shape.
    for (int s = (T4 << 2) + tid; s < total; s += stride)
        out[s] = interp1(xs[s], s_x, s_ys, s_lut, inv_w, c0);
}

extern "C" void kernel_launch(void* const* d_in, const int* in_sizes, int n_in,
                              void* d_out, int out_size) {
    const float* xs = (const float*)d_in[0];
    const float* xp = (const float*)d_in[1];
    const float* yp = (const float*)d_in[2];
    float* out = (float*)d_out;
    int total = in_sizes[0];
    int n = in_sizes[1];

    build_lut_kernel<<<(LUT_SIZE + 2 + 255) / 256, 256>>>(xp, n);

    size_t smem_bytes = (size_t)n * 12 + (size_t)(LUT_SIZE + 2) * 2;
    cudaFuncSetAttribute(interp_kernel,
                         cudaFuncAttributeMaxDynamicSharedMemorySize,
                         (int)smem_bytes);

    int sm_count = 148, dev = 0;
    cudaGetDevice(&dev);
    cudaDeviceGetAttribute(&sm_count, cudaDevAttrMultiProcessorCount, dev);
    if (sm_count <= 0) sm_count = 148;

    interp_kernel<<<sm_count, THREADS, smem_bytes>>>(xs, xp, yp, out, total, n);
}